// round 14
// baseline (speedup 1.0000x reference)
#include <cuda_runtime.h>
#include <math.h>

#define H 1024
#define V 50257
#define L 512
#define NB16 ((V + 15) / 16)     // 3142 blocks of 16 rows in k_logits
#define NLC 32                   // l-chunks in attn partial stage
#define NBLK 128                 // persistent pre-kernel grid (<148, all resident)

// ---------------- scratch (device globals; no allocations allowed) ----------
__device__ float g_s[L];              // raw attention scores
__device__ float g_part[NLC * H];     // partial attn_applied sums
__device__ float g_comb[2 * H];       // [embedded | attn_applied]
__device__ float g_x[H];              // relu(combined @ Wc^T + bc)
__device__ float g_h[H];              // h_new
__device__ float g_logits[V];
__device__ float g_pm[NB16];          // per-block max
__device__ float g_ps[NB16];          // per-block sum exp
__device__ int   g_bar_cnt[4];        // zero-init; releaser resets -> replay-safe
__device__ int   g_bar_flag[4];       // monotonic epochs across replays

__inline__ __device__ float warpSum(float v) {
    #pragma unroll
    for (int o = 16; o; o >>= 1) v += __shfl_xor_sync(0xffffffffu, v, o);
    return v;
}
__inline__ __device__ float warpMax(float v) {
    #pragma unroll
    for (int o = 16; o; o >>= 1) v = fmaxf(v, __shfl_xor_sync(0xffffffffu, v, o));
    return v;
}

// Grid barrier: monotonic flag epoch; counter reset by releaser BEFORE flag
// bump, so all state except the monotonically-growing flag returns to initial
// (replay-safe under graph capture). All blocks co-resident (NBLK <= SMs).
__device__ __forceinline__ void gridbar(int i) {
    __syncthreads();
    if (threadIdx.x == 0) {
        __threadfence();
        int v = atomicAdd(&g_bar_flag[i], 0);
        int old = atomicAdd(&g_bar_cnt[i], 1);
        if (old == NBLK - 1) {
            atomicExch(&g_bar_cnt[i], 0);
            atomicAdd(&g_bar_flag[i], 1);
        } else {
            while (atomicAdd(&g_bar_flag[i], 0) == v) { }
        }
    }
    __syncthreads();
}

// ---------------------------------------------------------------------------
// K_PRE: fused scores -> softmax+attn partials -> reduce+embed -> combine -> GRU
// 128 blocks x 256 threads, persistent, 4 grid barriers.
// ---------------------------------------------------------------------------
__global__ void __launch_bounds__(256) k_pre(
    const float* __restrict__ hid, const float* __restrict__ enc,
    const float* __restrict__ emb, const long long* __restrict__ tok,
    const float* __restrict__ wc,  const float* __restrict__ bc,
    const float* __restrict__ wih, const float* __restrict__ whh,
    const float* __restrict__ bih, const float* __restrict__ bhh,
    float* __restrict__ out_attn,  float* __restrict__ out_h)
{
    __shared__ float4 shv[512];            // 8KB staging, reused per phase
    __shared__ float red[8];
    __shared__ float bcast;
    float* shf = (float*)shv;

    int t = threadIdx.x;
    int warp = t >> 5, lane = t & 31;
    int b = blockIdx.x;

    // ---- Phase A: scores s[l] = dot(h0, enc[l]); warp-per-row --------------
    shv[t] = ((const float4*)hid)[t];      // stage h0 (1024 floats)
    __syncthreads();
    int gw = b * 8 + warp;                 // 0..1023
    if (gw < L) {
        const float4* e4 = (const float4*)(enc + (size_t)gw * H);
        float a0 = 0.f, a1 = 0.f;
        #pragma unroll
        for (int k = 0; k < 4; k++) {
            float4 ea = e4[lane + 32 * k],       ba = shv[lane + 32 * k];
            float4 eb = e4[lane + 32 * (k + 4)], bb = shv[lane + 32 * (k + 4)];
            a0 += ea.x * ba.x + ea.y * ba.y + ea.z * ba.z + ea.w * ba.w;
            a1 += eb.x * bb.x + eb.y * bb.y + eb.z * bb.z + eb.w * bb.w;
        }
        float acc = warpSum(a0 + a1);
        if (lane == 0) g_s[gw] = acc;
    }
    gridbar(0);

    // ---- Phase B: per-block softmax (redundant, 2KB) + attn partials -------
    {
        int hc = b & 3;                    // h-chunk 0..3
        int lc = b >> 2;                   // l-chunk 0..31 (16 l each)
        float s0 = g_s[t], s1 = g_s[t + 256];
        float m = warpMax(fmaxf(s0, s1));
        if (lane == 0) red[warp] = m;
        __syncthreads();
        if (t == 0) {
            float mm = red[0];
            #pragma unroll
            for (int i = 1; i < 8; i++) mm = fmaxf(mm, red[i]);
            bcast = mm;
        }
        __syncthreads();
        float M = bcast;
        float e0 = expf(s0 - M), e1 = expf(s1 - M);
        __syncthreads();
        float s = warpSum(e0 + e1);
        if (lane == 0) red[warp] = s;
        __syncthreads();
        if (t == 0) {
            float ss = 0.f;
            #pragma unroll
            for (int i = 0; i < 8; i++) ss += red[i];
            bcast = 1.f / ss;
        }
        __syncthreads();
        float inv = bcast;
        shf[t] = e0 * inv;                 // ws[0..511] in shf
        shf[t + 256] = e1 * inv;
        __syncthreads();

        if (hc == 0 && t < 16) out_attn[lc * 16 + t] = shf[lc * 16 + t];

        int h = hc * 256 + t;
        const float* ep = enc + (size_t)(lc * 16) * H + h;
        float acc = 0.f;
        #pragma unroll
        for (int l = 0; l < 16; l++) acc += shf[lc * 16 + l] * ep[(size_t)l * H];
        g_part[lc * H + h] = acc;
    }
    gridbar(1);

    // ---- Phase C: reduce partials -> comb[H..2H); embed -> comb[0..H) ------
    {
        int gid = b * 256 + t;
        if (gid < H) {
            float a = 0.f;
            #pragma unroll
            for (int i = 0; i < NLC; i++) a += g_part[i * H + gid];
            g_comb[H + gid] = a;
            g_comb[gid] = emb[(size_t)tok[0] * H + gid];
        }
    }
    gridbar(2);

    // ---- Phase D: x[row] = relu(Wc[row] . comb + bc); warp-per-row ---------
    shv[t] = ((const float4*)g_comb)[t];
    shv[t + 256] = ((const float4*)g_comb)[t + 256];
    __syncthreads();
    {
        int row = b * 8 + warp;            // 1024 rows == 1024 warps
        const float4* w4 = (const float4*)(wc + (size_t)row * 2 * H);
        float a0 = 0.f, a1 = 0.f;
        #pragma unroll
        for (int k = 0; k < 8; k++) {
            float4 wa = w4[lane + 32 * k];
            float4 ca = shv[lane + 32 * k];
            float4 wb = w4[256 + lane + 32 * k];
            float4 cb = shv[256 + lane + 32 * k];
            a0 += wa.x * ca.x + wa.y * ca.y + wa.z * ca.z + wa.w * ca.w;
            a1 += wb.x * cb.x + wb.y * cb.y + wb.z * cb.z + wb.w * cb.w;
        }
        float acc = warpSum(a0 + a1);
        if (lane == 0) g_x[row] = fmaxf(acc + bc[row], 0.f);
    }
    gridbar(3);

    // ---- Phase E: GRU; warp-per-h, all 6 dots in-warp ----------------------
    shv[t] = ((const float4*)g_x)[t];          // xs: shv[0..255]
    shv[t + 256] = ((const float4*)hid)[t];    // hs: shv[256..511]
    __syncthreads();
    {
        int h = b * 8 + warp;              // 1024 h == 1024 warps
        float di[3], dh[3];
        #pragma unroll
        for (int g = 0; g < 3; g++) {
            const float4* wi4 = (const float4*)(wih + ((size_t)g * H + h) * H);
            const float4* wh4 = (const float4*)(whh + ((size_t)g * H + h) * H);
            float ai = 0.f, ah = 0.f;
            #pragma unroll
            for (int k = 0; k < 8; k++) {
                float4 a = wi4[lane + 32 * k];
                float4 x = shv[lane + 32 * k];
                float4 c = wh4[lane + 32 * k];
                float4 hh = shv[256 + lane + 32 * k];
                ai += a.x * x.x + a.y * x.y + a.z * x.z + a.w * x.w;
                ah += c.x * hh.x + c.y * hh.y + c.z * hh.z + c.w * hh.w;
            }
            di[g] = warpSum(ai);
            dh[g] = warpSum(ah);
        }
        if (lane == 0) {
            float r = 1.f / (1.f + expf(-(di[0] + bih[h]         + dh[0] + bhh[h])));
            float z = 1.f / (1.f + expf(-(di[1] + bih[H + h]     + dh[1] + bhh[H + h])));
            float n = tanhf(di[2] + bih[2 * H + h] + r * (dh[2] + bhh[2 * H + h]));
            float hn = (1.f - z) * n + z * hid[h];
            g_h[h] = hn;
            out_h[h] = hn;
        }
    }
}

// ---------------------------------------------------------------------------
// K_LOGITS: logits + per-block partial logsumexp; 2 rows/warp, 16 rows/block.
// ---------------------------------------------------------------------------
__global__ void __launch_bounds__(256) k_logits(const float* __restrict__ ow,
                                                const float* __restrict__ ob) {
    __shared__ float4 hs[H / 4];
    __shared__ float lg[16];
    int t = threadIdx.x;
    hs[t] = ((const float4*)g_h)[t];
    __syncthreads();
    int warp = t >> 5, lane = t & 31;
    int v0 = blockIdx.x * 16 + warp * 2;
    float l0 = -INFINITY, l1 = -INFINITY;
    bool r0 = v0 < V, r1 = (v0 + 1) < V;
    const float4* w0 = (const float4*)(ow + (size_t)v0 * H);
    const float4* w1 = (const float4*)(ow + (size_t)(v0 + 1) * H);
    float acc0 = 0.f, acc1 = 0.f;
    if (r1) {
        #pragma unroll
        for (int k = 0; k < 8; k++) {
            float4 bq = hs[lane + 32 * k];
            float4 a0 = w0[lane + 32 * k];
            float4 a1 = w1[lane + 32 * k];
            acc0 += a0.x * bq.x + a0.y * bq.y + a0.z * bq.z + a0.w * bq.w;
            acc1 += a1.x * bq.x + a1.y * bq.y + a1.z * bq.z + a1.w * bq.w;
        }
    } else if (r0) {
        #pragma unroll
        for (int k = 0; k < 8; k++) {
            float4 bq = hs[lane + 32 * k];
            float4 a0 = w0[lane + 32 * k];
            acc0 += a0.x * bq.x + a0.y * bq.y + a0.z * bq.z + a0.w * bq.w;
        }
    }
    acc0 = warpSum(acc0);
    acc1 = warpSum(acc1);
    if (lane == 0) {
        if (r0) { l0 = acc0 + ob[v0];     g_logits[v0] = l0; }
        if (r1) { l1 = acc1 + ob[v0 + 1]; g_logits[v0 + 1] = l1; }
        lg[warp * 2]     = l0;
        lg[warp * 2 + 1] = l1;
    }
    __syncthreads();
    if (t == 0) {
        float m = -INFINITY;
        #pragma unroll
        for (int i = 0; i < 16; i++) m = fmaxf(m, lg[i]);
        float s = 0.f;
        #pragma unroll
        for (int i = 0; i < 16; i++) s += (lg[i] == -INFINITY) ? 0.f : expf(lg[i] - m);
        g_pm[blockIdx.x] = m;
        g_ps[blockIdx.x] = s;
    }
}

// K_LOGP: per-block redundant LSE combine (from L2) + logp write. 99 x 512
__global__ void k_logp(float* __restrict__ out) {
    __shared__ float sm[16], ss[16];
    __shared__ float bM, bLS;
    int t = threadIdx.x;
    float m = -INFINITY, s = 0.f;
    for (int i = t; i < NB16; i += 512) {
        float bm = g_pm[i], bs = g_ps[i];
        float nm = fmaxf(m, bm);
        s = s * expf(m - nm) + bs * expf(bm - nm);
        m = nm;
    }
    #pragma unroll
    for (int o = 16; o; o >>= 1) {
        float om = __shfl_xor_sync(0xffffffffu, m, o);
        float os = __shfl_xor_sync(0xffffffffu, s, o);
        float nm = fmaxf(m, om);
        s = s * expf(m - nm) + os * expf(om - nm);
        m = nm;
    }
    if ((t & 31) == 0) { sm[t >> 5] = m; ss[t >> 5] = s; }
    __syncthreads();
    if (t == 0) {
        float M = sm[0], S = ss[0];
        #pragma unroll
        for (int i = 1; i < 16; i++) {
            float nm = fmaxf(M, sm[i]);
            S = S * expf(M - nm) + ss[i] * expf(sm[i] - nm);
            M = nm;
        }
        bM = M;
        bLS = logf(S);
    }
    __syncthreads();
    float M = bM, LS = bLS;
    for (int v = blockIdx.x * 512 + t; v < V; v += gridDim.x * 512)
        out[v] = g_logits[v] - M - LS;
}

extern "C" void kernel_launch(void* const* d_in, const int* in_sizes, int n_in,
                              void* d_out, int out_size) {
    const long long* tok = (const long long*)d_in[0];
    const float* hid  = (const float*)d_in[1];
    const float* enc  = (const float*)d_in[2];
    const float* emb  = (const float*)d_in[3];
    const float* wc   = (const float*)d_in[4];
    const float* bc   = (const float*)d_in[5];
    const float* wih  = (const float*)d_in[6];
    const float* whh  = (const float*)d_in[7];
    const float* bih  = (const float*)d_in[8];
    const float* bhh  = (const float*)d_in[9];
    const float* ow   = (const float*)d_in[10];
    const float* ob   = (const float*)d_in[11];

    float* out = (float*)d_out;
    float* out_logp = out;
    float* out_h    = out + V;
    float* out_attn = out + V + H;

    k_pre<<<NBLK, 256>>>(hid, enc, emb, tok, wc, bc, wih, whh, bih, bhh,
                         out_attn, out_h);
    k_logits<<<NB16, 256>>>(ow, ob);
    k_logp<<<99, 512>>>(out_logp);
}

// round 15
// speedup vs baseline: 1.0033x; 1.0033x over previous
#include <cuda_runtime.h>
#include <math.h>

#define H 1024
#define V 50257
#define L 512
#define NB16 ((V + 15) / 16)     // 3142 blocks of 16 rows in k_logits
#define NLC 32                   // l-chunks in attn partial stage
#define NBLK 128                 // persistent pre-kernel grid (<148, all resident)

// ---------------- scratch (device globals; no allocations allowed) ----------
__device__ float g_s[L];              // raw attention scores
__device__ float g_part[NLC * H];     // partial attn_applied sums
__device__ float g_comb[2 * H];       // [embedded | attn_applied]
__device__ float g_x[H];              // relu(combined @ Wc^T + bc)
__device__ float g_h[H];              // h_new
__device__ float g_logits[V];
__device__ float g_pm[NB16];          // per-block max
__device__ float g_ps[NB16];          // per-block sum exp
__device__ int   g_bar_cnt[4];        // zero-init; releaser resets -> replay-safe
__device__ int   g_bar_flag[4];       // monotonic epochs across replays

__inline__ __device__ float warpSum(float v) {
    #pragma unroll
    for (int o = 16; o; o >>= 1) v += __shfl_xor_sync(0xffffffffu, v, o);
    return v;
}
__inline__ __device__ float warpMax(float v) {
    #pragma unroll
    for (int o = 16; o; o >>= 1) v = fmaxf(v, __shfl_xor_sync(0xffffffffu, v, o));
    return v;
}

// Grid barrier: monotonic flag epoch; counter reset by releaser BEFORE flag
// bump, so all state except the monotonically-growing flag returns to initial
// (replay-safe under graph capture). All blocks co-resident (NBLK <= SMs).
__device__ __forceinline__ void gridbar(int i) {
    __syncthreads();
    if (threadIdx.x == 0) {
        __threadfence();
        int v = atomicAdd(&g_bar_flag[i], 0);
        int old = atomicAdd(&g_bar_cnt[i], 1);
        if (old == NBLK - 1) {
            atomicExch(&g_bar_cnt[i], 0);
            atomicAdd(&g_bar_flag[i], 1);
        } else {
            while (atomicAdd(&g_bar_flag[i], 0) == v) { }
        }
    }
    __syncthreads();
}

// ---------------------------------------------------------------------------
// K_PRE: fused scores -> softmax+attn partials -> reduce+embed -> combine -> GRU
// 128 blocks x 256 threads, persistent, 4 grid barriers.
// ---------------------------------------------------------------------------
__global__ void __launch_bounds__(256) k_pre(
    const float* __restrict__ hid, const float* __restrict__ enc,
    const float* __restrict__ emb, const long long* __restrict__ tok,
    const float* __restrict__ wc,  const float* __restrict__ bc,
    const float* __restrict__ wih, const float* __restrict__ whh,
    const float* __restrict__ bih, const float* __restrict__ bhh,
    float* __restrict__ out_attn,  float* __restrict__ out_h)
{
    __shared__ float4 shv[512];            // 8KB staging, reused per phase
    __shared__ float red[8];
    __shared__ float bcast;
    float* shf = (float*)shv;

    int t = threadIdx.x;
    int warp = t >> 5, lane = t & 31;
    int b = blockIdx.x;

    // ---- Phase A: scores s[l] = dot(h0, enc[l]); warp-per-row --------------
    shv[t] = ((const float4*)hid)[t];      // stage h0 (1024 floats)
    __syncthreads();
    int gw = b * 8 + warp;                 // 0..1023
    if (gw < L) {
        const float4* e4 = (const float4*)(enc + (size_t)gw * H);
        float a0 = 0.f, a1 = 0.f;
        #pragma unroll
        for (int k = 0; k < 4; k++) {
            float4 ea = e4[lane + 32 * k],       ba = shv[lane + 32 * k];
            float4 eb = e4[lane + 32 * (k + 4)], bb = shv[lane + 32 * (k + 4)];
            a0 += ea.x * ba.x + ea.y * ba.y + ea.z * ba.z + ea.w * ba.w;
            a1 += eb.x * bb.x + eb.y * bb.y + eb.z * bb.z + eb.w * bb.w;
        }
        float acc = warpSum(a0 + a1);
        if (lane == 0) g_s[gw] = acc;
    }
    gridbar(0);

    // ---- Phase B: per-block softmax (redundant, 2KB) + attn partials -------
    {
        int hc = b & 3;                    // h-chunk 0..3
        int lc = b >> 2;                   // l-chunk 0..31 (16 l each)
        float s0 = g_s[t], s1 = g_s[t + 256];
        float m = warpMax(fmaxf(s0, s1));
        if (lane == 0) red[warp] = m;
        __syncthreads();
        if (t == 0) {
            float mm = red[0];
            #pragma unroll
            for (int i = 1; i < 8; i++) mm = fmaxf(mm, red[i]);
            bcast = mm;
        }
        __syncthreads();
        float M = bcast;
        float e0 = expf(s0 - M), e1 = expf(s1 - M);
        __syncthreads();
        float s = warpSum(e0 + e1);
        if (lane == 0) red[warp] = s;
        __syncthreads();
        if (t == 0) {
            float ss = 0.f;
            #pragma unroll
            for (int i = 0; i < 8; i++) ss += red[i];
            bcast = 1.f / ss;
        }
        __syncthreads();
        float inv = bcast;
        shf[t] = e0 * inv;                 // ws[0..511] in shf
        shf[t + 256] = e1 * inv;
        __syncthreads();

        if (hc == 0 && t < 16) out_attn[lc * 16 + t] = shf[lc * 16 + t];

        int h = hc * 256 + t;
        const float* ep = enc + (size_t)(lc * 16) * H + h;
        float acc = 0.f;
        #pragma unroll
        for (int l = 0; l < 16; l++) acc += shf[lc * 16 + l] * ep[(size_t)l * H];
        g_part[lc * H + h] = acc;
    }
    gridbar(1);

    // ---- Phase C: reduce partials -> comb[H..2H); embed -> comb[0..H) ------
    {
        int gid = b * 256 + t;
        if (gid < H) {
            float a = 0.f;
            #pragma unroll
            for (int i = 0; i < NLC; i++) a += g_part[i * H + gid];
            g_comb[H + gid] = a;
            g_comb[gid] = emb[(size_t)tok[0] * H + gid];
        }
    }
    gridbar(2);

    // ---- Phase D: x[row] = relu(Wc[row] . comb + bc); warp-per-row ---------
    shv[t] = ((const float4*)g_comb)[t];
    shv[t + 256] = ((const float4*)g_comb)[t + 256];
    __syncthreads();
    {
        int row = b * 8 + warp;            // 1024 rows == 1024 warps
        const float4* w4 = (const float4*)(wc + (size_t)row * 2 * H);
        float a0 = 0.f, a1 = 0.f;
        #pragma unroll
        for (int k = 0; k < 8; k++) {
            float4 wa = w4[lane + 32 * k];
            float4 ca = shv[lane + 32 * k];
            float4 wb = w4[256 + lane + 32 * k];
            float4 cb = shv[256 + lane + 32 * k];
            a0 += wa.x * ca.x + wa.y * ca.y + wa.z * ca.z + wa.w * ca.w;
            a1 += wb.x * cb.x + wb.y * cb.y + wb.z * cb.z + wb.w * cb.w;
        }
        float acc = warpSum(a0 + a1);
        if (lane == 0) g_x[row] = fmaxf(acc + bc[row], 0.f);
    }
    gridbar(3);

    // ---- Phase E: GRU; warp-per-h, all 6 dots in-warp ----------------------
    shv[t] = ((const float4*)g_x)[t];          // xs: shv[0..255]
    shv[t + 256] = ((const float4*)hid)[t];    // hs: shv[256..511]
    __syncthreads();
    {
        int h = b * 8 + warp;              // 1024 h == 1024 warps
        float di[3], dh[3];
        #pragma unroll
        for (int g = 0; g < 3; g++) {
            const float4* wi4 = (const float4*)(wih + ((size_t)g * H + h) * H);
            const float4* wh4 = (const float4*)(whh + ((size_t)g * H + h) * H);
            float ai = 0.f, ah = 0.f;
            #pragma unroll
            for (int k = 0; k < 8; k++) {
                float4 a = wi4[lane + 32 * k];
                float4 x = shv[lane + 32 * k];
                float4 c = wh4[lane + 32 * k];
                float4 hh = shv[256 + lane + 32 * k];
                ai += a.x * x.x + a.y * x.y + a.z * x.z + a.w * x.w;
                ah += c.x * hh.x + c.y * hh.y + c.z * hh.z + c.w * hh.w;
            }
            di[g] = warpSum(ai);
            dh[g] = warpSum(ah);
        }
        if (lane == 0) {
            float r = 1.f / (1.f + expf(-(di[0] + bih[h]         + dh[0] + bhh[h])));
            float z = 1.f / (1.f + expf(-(di[1] + bih[H + h]     + dh[1] + bhh[H + h])));
            float n = tanhf(di[2] + bih[2 * H + h] + r * (dh[2] + bhh[2 * H + h]));
            float hn = (1.f - z) * n + z * hid[h];
            g_h[h] = hn;
            out_h[h] = hn;
        }
    }
}

// ---------------------------------------------------------------------------
// K_LOGITS: logits + per-block partial logsumexp; 2 rows/warp, 16 rows/block.
// ---------------------------------------------------------------------------
__global__ void __launch_bounds__(256) k_logits(const float* __restrict__ ow,
                                                const float* __restrict__ ob) {
    __shared__ float4 hs[H / 4];
    __shared__ float lg[16];
    int t = threadIdx.x;
    hs[t] = ((const float4*)g_h)[t];
    __syncthreads();
    int warp = t >> 5, lane = t & 31;
    int v0 = blockIdx.x * 16 + warp * 2;
    float l0 = -INFINITY, l1 = -INFINITY;
    bool r0 = v0 < V, r1 = (v0 + 1) < V;
    const float4* w0 = (const float4*)(ow + (size_t)v0 * H);
    const float4* w1 = (const float4*)(ow + (size_t)(v0 + 1) * H);
    float acc0 = 0.f, acc1 = 0.f;
    if (r1) {
        #pragma unroll
        for (int k = 0; k < 8; k++) {
            float4 bq = hs[lane + 32 * k];
            float4 a0 = w0[lane + 32 * k];
            float4 a1 = w1[lane + 32 * k];
            acc0 += a0.x * bq.x + a0.y * bq.y + a0.z * bq.z + a0.w * bq.w;
            acc1 += a1.x * bq.x + a1.y * bq.y + a1.z * bq.z + a1.w * bq.w;
        }
    } else if (r0) {
        #pragma unroll
        for (int k = 0; k < 8; k++) {
            float4 bq = hs[lane + 32 * k];
            float4 a0 = w0[lane + 32 * k];
            acc0 += a0.x * bq.x + a0.y * bq.y + a0.z * bq.z + a0.w * bq.w;
        }
    }
    acc0 = warpSum(acc0);
    acc1 = warpSum(acc1);
    if (lane == 0) {
        if (r0) { l0 = acc0 + ob[v0];     g_logits[v0] = l0; }
        if (r1) { l1 = acc1 + ob[v0 + 1]; g_logits[v0 + 1] = l1; }
        lg[warp * 2]     = l0;
        lg[warp * 2 + 1] = l1;
    }
    __syncthreads();
    if (t == 0) {
        float m = -INFINITY;
        #pragma unroll
        for (int i = 0; i < 16; i++) m = fmaxf(m, lg[i]);
        float s = 0.f;
        #pragma unroll
        for (int i = 0; i < 16; i++) s += (lg[i] == -INFINITY) ? 0.f : expf(lg[i] - m);
        g_pm[blockIdx.x] = m;
        g_ps[blockIdx.x] = s;
    }
}

// K_LOGP: per-block redundant LSE combine (from L2) + logp write. 99 x 512
__global__ void k_logp(float* __restrict__ out) {
    __shared__ float sm[16], ss[16];
    __shared__ float bM, bLS;
    int t = threadIdx.x;
    float m = -INFINITY, s = 0.f;
    for (int i = t; i < NB16; i += 512) {
        float bm = g_pm[i], bs = g_ps[i];
        float nm = fmaxf(m, bm);
        s = s * expf(m - nm) + bs * expf(bm - nm);
        m = nm;
    }
    #pragma unroll
    for (int o = 16; o; o >>= 1) {
        float om = __shfl_xor_sync(0xffffffffu, m, o);
        float os = __shfl_xor_sync(0xffffffffu, s, o);
        float nm = fmaxf(m, om);
        s = s * expf(m - nm) + os * expf(om - nm);
        m = nm;
    }
    if ((t & 31) == 0) { sm[t >> 5] = m; ss[t >> 5] = s; }
    __syncthreads();
    if (t == 0) {
        float M = sm[0], S = ss[0];
        #pragma unroll
        for (int i = 1; i < 16; i++) {
            float nm = fmaxf(M, sm[i]);
            S = S * expf(M - nm) + ss[i] * expf(sm[i] - nm);
            M = nm;
        }
        bM = M;
        bLS = logf(S);
    }
    __syncthreads();
    float M = bM, LS = bLS;
    for (int v = blockIdx.x * 512 + t; v < V; v += gridDim.x * 512)
        out[v] = g_logits[v] - M - LS;
}

extern "C" void kernel_launch(void* const* d_in, const int* in_sizes, int n_in,
                              void* d_out, int out_size) {
    const long long* tok = (const long long*)d_in[0];
    const float* hid  = (const float*)d_in[1];
    const float* enc  = (const float*)d_in[2];
    const float* emb  = (const float*)d_in[3];
    const float* wc   = (const float*)d_in[4];
    const float* bc   = (const float*)d_in[5];
    const float* wih  = (const float*)d_in[6];
    const float* whh  = (const float*)d_in[7];
    const float* bih  = (const float*)d_in[8];
    const float* bhh  = (const float*)d_in[9];
    const float* ow   = (const float*)d_in[10];
    const float* ob   = (const float*)d_in[11];

    float* out = (float*)d_out;
    float* out_logp = out;
    float* out_h    = out + V;
    float* out_attn = out + V + H;

    k_pre<<<NBLK, 256>>>(hid, enc, emb, tok, wc, bc, wih, whh, bih, bhh,
                         out_attn, out_h);
    k_logits<<<NB16, 256>>>(ow, ob);
    k_logp<<<99, 512>>>(out_logp);
}

// round 16
// speedup vs baseline: 1.0638x; 1.0603x over previous
#include <cuda_runtime.h>
#include <math.h>

#define H 1024
#define V 50257
#define L 512
#define NB16 ((V + 15) / 16)     // 3142 blocks of 16 rows in k_logits
#define NLC 32                   // l-chunks in attn partial stage
#define NG 6144                  // GRU GEMV rows: [wih(3H) | whh(3H)]

// ---------------- scratch (device globals; no allocations allowed) ----------
__device__ float g_s[L];              // raw attention scores
__device__ float g_part[NLC * H];     // partial attn_applied sums
__device__ float g_comb[2 * H];       // [embedded | attn_applied]
__device__ float g_x[H];              // relu(combined @ Wc^T + bc)
__device__ float g_gates[NG];         // gi(3H) then gh(3H)
__device__ float g_h[H];              // h_new
__device__ float g_logits[V];
__device__ float g_pm[NB16];          // per-block max
__device__ float g_ps[NB16];          // per-block sum exp

__inline__ __device__ float warpSum(float v) {
    #pragma unroll
    for (int o = 16; o; o >>= 1) v += __shfl_xor_sync(0xffffffffu, v, o);
    return v;
}
__inline__ __device__ float warpMax(float v) {
    #pragma unroll
    for (int o = 16; o; o >>= 1) v = fmaxf(v, __shfl_xor_sync(0xffffffffu, v, o));
    return v;
}

// K1: s[l] = dot(h0, enc[l]); warp-per-row, 64 blocks x 256
__global__ void k_scores(const float* __restrict__ hid, const float* __restrict__ enc) {
    __shared__ float4 hs[H / 4];
    int t = threadIdx.x;
    hs[t] = ((const float4*)hid)[t];
    __syncthreads();
    int warp = t >> 5, lane = t & 31;
    int l = blockIdx.x * 8 + warp;
    const float4* e4 = (const float4*)(enc + (size_t)l * H);
    float a0 = 0.f, a1 = 0.f;
    #pragma unroll
    for (int k = 0; k < 4; k++) {
        float4 ea = e4[lane + 32 * k],       ba = hs[lane + 32 * k];
        float4 eb = e4[lane + 32 * (k + 4)], bb = hs[lane + 32 * (k + 4)];
        a0 += ea.x * ba.x + ea.y * ba.y + ea.z * ba.z + ea.w * ba.w;
        a1 += eb.x * bb.x + eb.y * bb.y + eb.z * bb.z + eb.w * bb.w;
    }
    float acc = warpSum(a0 + a1);
    if (lane == 0) g_s[l] = acc;
}

// K2: fused softmax (redundant per block) + partial attn apply.
// grid 128 = 4 h-chunks x 32 l-chunks (16 l each); block 256.
__global__ void k_attnps(const float* __restrict__ enc, float* __restrict__ out_attn) {
    __shared__ float ws[L];
    __shared__ float red[8];
    __shared__ float bcast;
    int t = threadIdx.x;
    int hc = blockIdx.x & 3;
    int lc = blockIdx.x >> 2;      // 0..31

    float s0 = g_s[t], s1 = g_s[t + 256];
    float m = warpMax(fmaxf(s0, s1));
    if ((t & 31) == 0) red[t >> 5] = m;
    __syncthreads();
    if (t == 0) {
        float mm = red[0];
        #pragma unroll
        for (int i = 1; i < 8; i++) mm = fmaxf(mm, red[i]);
        bcast = mm;
    }
    __syncthreads();
    float M = bcast;
    float e0 = expf(s0 - M), e1 = expf(s1 - M);
    __syncthreads();
    float s = warpSum(e0 + e1);
    if ((t & 31) == 0) red[t >> 5] = s;
    __syncthreads();
    if (t == 0) {
        float ss = 0.f;
        #pragma unroll
        for (int i = 0; i < 8; i++) ss += red[i];
        bcast = 1.f / ss;
    }
    __syncthreads();
    float inv = bcast;
    ws[t] = e0 * inv;
    ws[t + 256] = e1 * inv;
    __syncthreads();

    if (hc == 0 && t < 16) out_attn[lc * 16 + t] = ws[lc * 16 + t];

    int h = hc * 256 + t;
    const float* ep = enc + (size_t)(lc * 16) * H + h;
    float acc = 0.f;
    #pragma unroll
    for (int l = 0; l < 16; l++) acc += ws[lc * 16 + l] * ep[(size_t)l * H];
    g_part[lc * H + h] = acc;
}

// K3: reduce partials -> combined[H..2H); embedded gather -> combined[0..H)
__global__ void k_attnr(const float* __restrict__ emb, const long long* __restrict__ tok) {
    int h = blockIdx.x * 256 + threadIdx.x;
    float a = 0.f;
    #pragma unroll
    for (int i = 0; i < NLC; i++) a += g_part[i * H + h];
    g_comb[H + h] = a;
    g_comb[h] = emb[(size_t)tok[0] * H + h];
}

// K4: x[row] = relu(dot(Wc[row], comb)+bc); 1 row/warp, 16 batched float4
// loads in 2 chains. 128 blocks x 256.
__global__ void __launch_bounds__(256) k_combine(const float* __restrict__ wc,
                                                 const float* __restrict__ bc) {
    __shared__ float4 cs[2 * H / 4];
    int t = threadIdx.x;
    cs[t] = ((const float4*)g_comb)[t];
    cs[t + 256] = ((const float4*)g_comb)[t + 256];
    __syncthreads();
    int warp = t >> 5, lane = t & 31;
    int row = blockIdx.x * 8 + warp;
    const float4* w4 = (const float4*)(wc + (size_t)row * 2 * H);
    float a0 = 0.f, a1 = 0.f;
    #pragma unroll
    for (int k = 0; k < 8; k++) {
        float4 wa = w4[lane + 32 * k];
        float4 ca = cs[lane + 32 * k];
        float4 wb = w4[256 + lane + 32 * k];
        float4 cb = cs[256 + lane + 32 * k];
        a0 += wa.x * ca.x + wa.y * ca.y + wa.z * ca.z + wa.w * ca.w;
        a1 += wb.x * cb.x + wb.y * cb.y + wb.z * cb.z + wb.w * cb.w;
    }
    float acc = warpSum(a0 + a1);
    if (lane == 0) g_x[row] = fmaxf(acc + bc[row], 0.f);
}

// K5: GRU dots as flat 6144-row GEMV (k_logits geometry: 2 rows/warp,
// 16 rows/block, 16 batched loads). rows [0,3H): wih . x; [3H,6H): whh . h0.
__global__ void __launch_bounds__(256) k_gemv6(const float* __restrict__ wih,
                                               const float* __restrict__ whh,
                                               const float* __restrict__ hid) {
    __shared__ float4 xs[H / 4];   // vector for this block's rows
    int t = threadIdx.x;
    bool hi = blockIdx.x >= 192;                    // rows >= 3072 -> whh side
    xs[t] = hi ? ((const float4*)hid)[t] : ((const float4*)g_x)[t];
    __syncthreads();
    int warp = t >> 5, lane = t & 31;
    int r0 = blockIdx.x * 16 + warp * 2;            // 0..6142
    const float* base = hi ? (whh - (size_t)3 * H * H) : wih;   // row index stays global
    const float4* w0 = (const float4*)(base + (size_t)r0 * H);
    const float4* w1 = (const float4*)(base + (size_t)(r0 + 1) * H);
    float acc0 = 0.f, acc1 = 0.f;
    #pragma unroll
    for (int k = 0; k < 8; k++) {
        float4 b  = xs[lane + 32 * k];
        float4 a0 = w0[lane + 32 * k];
        float4 a1 = w1[lane + 32 * k];
        acc0 += a0.x * b.x + a0.y * b.y + a0.z * b.z + a0.w * b.w;
        acc1 += a1.x * b.x + a1.y * b.y + a1.z * b.z + a1.w * b.w;
    }
    acc0 = warpSum(acc0);
    acc1 = warpSum(acc1);
    if (lane == 0) {
        g_gates[r0]     = acc0;
        g_gates[r0 + 1] = acc1;
    }
}

// K6: GRU gates; 4 blocks x 256, one thread per h.
__global__ void k_gate(const float* __restrict__ bih, const float* __restrict__ bhh,
                       const float* __restrict__ hid, float* __restrict__ out_h) {
    int h = blockIdx.x * 256 + threadIdx.x;
    float gi_r = g_gates[h],           gh_r = g_gates[3 * H + h];
    float gi_z = g_gates[H + h],       gh_z = g_gates[4 * H + h];
    float gi_n = g_gates[2 * H + h],   gh_n = g_gates[5 * H + h];
    float r = 1.f / (1.f + expf(-(gi_r + bih[h]         + gh_r + bhh[h])));
    float z = 1.f / (1.f + expf(-(gi_z + bih[H + h]     + gh_z + bhh[H + h])));
    float n = tanhf(gi_n + bih[2 * H + h] + r * (gh_n + bhh[2 * H + h]));
    float hn = (1.f - z) * n + z * hid[h];
    g_h[h] = hn;
    out_h[h] = hn;
}

// K7: logits + per-block partial logsumexp; 2 rows/warp, 16 rows/block.
__global__ void __launch_bounds__(256) k_logits(const float* __restrict__ ow,
                                                const float* __restrict__ ob) {
    __shared__ float4 hs[H / 4];
    __shared__ float lg[16];
    int t = threadIdx.x;
    hs[t] = ((const float4*)g_h)[t];
    __syncthreads();
    int warp = t >> 5, lane = t & 31;
    int v0 = blockIdx.x * 16 + warp * 2;
    float l0 = -INFINITY, l1 = -INFINITY;
    bool r0 = v0 < V, r1 = (v0 + 1) < V;
    const float4* w0 = (const float4*)(ow + (size_t)v0 * H);
    const float4* w1 = (const float4*)(ow + (size_t)(v0 + 1) * H);
    float acc0 = 0.f, acc1 = 0.f;
    if (r1) {
        #pragma unroll
        for (int k = 0; k < 8; k++) {
            float4 bq = hs[lane + 32 * k];
            float4 a0 = w0[lane + 32 * k];
            float4 a1 = w1[lane + 32 * k];
            acc0 += a0.x * bq.x + a0.y * bq.y + a0.z * bq.z + a0.w * bq.w;
            acc1 += a1.x * bq.x + a1.y * bq.y + a1.z * bq.z + a1.w * bq.w;
        }
    } else if (r0) {
        #pragma unroll
        for (int k = 0; k < 8; k++) {
            float4 bq = hs[lane + 32 * k];
            float4 a0 = w0[lane + 32 * k];
            acc0 += a0.x * bq.x + a0.y * bq.y + a0.z * bq.z + a0.w * bq.w;
        }
    }
    acc0 = warpSum(acc0);
    acc1 = warpSum(acc1);
    if (lane == 0) {
        if (r0) { l0 = acc0 + ob[v0];     g_logits[v0] = l0; }
        if (r1) { l1 = acc1 + ob[v0 + 1]; g_logits[v0 + 1] = l1; }
        lg[warp * 2]     = l0;
        lg[warp * 2 + 1] = l1;
    }
    __syncthreads();
    if (t == 0) {
        float m = -INFINITY;
        #pragma unroll
        for (int i = 0; i < 16; i++) m = fmaxf(m, lg[i]);
        float s = 0.f;
        #pragma unroll
        for (int i = 0; i < 16; i++) s += (lg[i] == -INFINITY) ? 0.f : expf(lg[i] - m);
        g_pm[blockIdx.x] = m;
        g_ps[blockIdx.x] = s;
    }
}

// K8: per-block redundant LSE combine (from L2) + logp write. 99 x 512
__global__ void k_logp(float* __restrict__ out) {
    __shared__ float sm[16], ss[16];
    __shared__ float bM, bLS;
    int t = threadIdx.x;
    float m = -INFINITY, s = 0.f;
    for (int i = t; i < NB16; i += 512) {
        float bm = g_pm[i], bs = g_ps[i];
        float nm = fmaxf(m, bm);
        s = s * expf(m - nm) + bs * expf(bm - nm);
        m = nm;
    }
    #pragma unroll
    for (int o = 16; o; o >>= 1) {
        float om = __shfl_xor_sync(0xffffffffu, m, o);
        float os = __shfl_xor_sync(0xffffffffu, s, o);
        float nm = fmaxf(m, om);
        s = s * expf(m - nm) + os * expf(om - nm);
        m = nm;
    }
    if ((t & 31) == 0) { sm[t >> 5] = m; ss[t >> 5] = s; }
    __syncthreads();
    if (t == 0) {
        float M = sm[0], S = ss[0];
        #pragma unroll
        for (int i = 1; i < 16; i++) {
            float nm = fmaxf(M, sm[i]);
            S = S * expf(M - nm) + ss[i] * expf(sm[i] - nm);
            M = nm;
        }
        bM = M;
        bLS = logf(S);
    }
    __syncthreads();
    float M = bM, LS = bLS;
    for (int v = blockIdx.x * 512 + t; v < V; v += gridDim.x * 512)
        out[v] = g_logits[v] - M - LS;
}

extern "C" void kernel_launch(void* const* d_in, const int* in_sizes, int n_in,
                              void* d_out, int out_size) {
    const long long* tok = (const long long*)d_in[0];
    const float* hid  = (const float*)d_in[1];
    const float* enc  = (const float*)d_in[2];
    const float* emb  = (const float*)d_in[3];
    const float* wc   = (const float*)d_in[4];
    const float* bc   = (const float*)d_in[5];
    const float* wih  = (const float*)d_in[6];
    const float* whh  = (const float*)d_in[7];
    const float* bih  = (const float*)d_in[8];
    const float* bhh  = (const float*)d_in[9];
    const float* ow   = (const float*)d_in[10];
    const float* ob   = (const float*)d_in[11];

    float* out = (float*)d_out;
    float* out_logp = out;
    float* out_h    = out + V;
    float* out_attn = out + V + H;

    k_scores<<<L / 8, 256>>>(hid, enc);
    k_attnps<<<128, 256>>>(enc, out_attn);
    k_attnr<<<H / 256, 256>>>(emb, tok);
    k_combine<<<H / 8, 256>>>(wc, bc);
    k_gemv6<<<NG / 16, 256>>>(wih, whh, hid);
    k_gate<<<H / 256, 256>>>(bih, bhh, hid, out_h);
    k_logits<<<NB16, 256>>>(ow, ob);
    k_logp<<<99, 512>>>(out_logp);
}